// round 6
// baseline (speedup 1.0000x reference)
#include <cuda_runtime.h>
#include <math_constants.h>

#define N 512
#define MARGIN 0.3f
#define NBLK 256           // 128 tiles x 2 K-halves
#define NTHR 256
#define TROWS 32           // tile rows
#define TCOLS 64           // tile cols
#define KH4 16             // float4 per row per K-half (64 floats)
#define PADK 68            // floats per smem row (17 float4, odd -> conflict-free)

__device__ float g_p0[N * N];   // K-half 0 partial: ni_h + nj_h - 2*dot_h
__device__ float g_p1[N * N];   // K-half 1 partial
__device__ double g_sum;
__device__ unsigned long long g_cnt;
__device__ unsigned g_arrive;   // reset by last block each launch
__device__ unsigned g_done;

__global__ __launch_bounds__(NTHR, 2) void fused_kernel(
    const float* __restrict__ x,
    const int* __restrict__ labels,
    float* __restrict__ out)
{
    __shared__ __align__(16) float Xj[TCOLS][PADK];   // 17408 B
    __shared__ __align__(16) union SU {
        float Xi[TROWS][PADK];                        // 8704 B (phase 1)
        struct {
            float drow[N];
            int   slbl[N];
            int   plist[96];
            int   pcount;
            float red_s[8];
            unsigned red_c[8];
        } p2;
    } u;
    __shared__ float sni[TROWS], snj[TCOLS];

    const int tid  = threadIdx.x;
    const int lane = tid & 31;
    const int w    = tid >> 5;
    const int bid  = blockIdx.x;

    // ======================= Phase 1: K-half partial tile =================
    const int tile = bid >> 1;
    const int kh   = bid & 1;
    const int i0   = (tile >> 3) * TROWS;    // 16 row-tiles
    const int j0   = (tile & 7)  * TCOLS;    // 8  col-tiles
    const int koff = kh * KH4;               // float4 offset into each row

    const float4* gx = reinterpret_cast<const float4*>(x);

    // Stage Xi (32 rows x 16 float4) and Xj (64 rows x 16 float4), coalesced.
#pragma unroll
    for (int t = tid; t < TROWS * KH4; t += NTHR) {
        const int r = t >> 4, c = t & 15;
        *reinterpret_cast<float4*>(&u.Xi[r][c * 4]) = gx[(i0 + r) * 32 + koff + c];
    }
#pragma unroll
    for (int t = tid; t < TCOLS * KH4; t += NTHR) {
        const int r = t >> 4, c = t & 15;
        *reinterpret_cast<float4*>(&Xj[r][c * 4]) = gx[(j0 + r) * 32 + koff + c];
    }
    __syncthreads();

    // Partial row norms over this K-half (96 threads, conflict-free rows).
    if (tid < TROWS + TCOLS) {
        const float* row = (tid < TROWS) ? &u.Xi[tid][0] : &Xj[tid - TROWS][0];
        float s = 0.f;
#pragma unroll
        for (int c4 = 0; c4 < KH4; c4++) {
            float4 v = *reinterpret_cast<const float4*>(row + c4 * 4);
            s = fmaf(v.x, v.x, fmaf(v.y, v.y, fmaf(v.z, v.z, fmaf(v.w, v.w, s))));
        }
        if (tid < TROWS) sni[tid] = s; else snj[tid - TROWS] = s;
    }
    __syncthreads();

    // 2x4 register tile: rows {2ty, 2ty+1}, cols {tx, tx+16, tx+32, tx+48}
    const int tx = tid & 15, ty = tid >> 4;   // ty 0..15
    const int r0 = 2 * ty;
    float a0c0=0.f, a0c1=0.f, a0c2=0.f, a0c3=0.f;
    float a1c0=0.f, a1c1=0.f, a1c2=0.f, a1c3=0.f;

#pragma unroll
    for (int c4 = 0; c4 < KH4; c4++) {
        float4 a0 = *reinterpret_cast<const float4*>(&u.Xi[r0    ][c4 * 4]);
        float4 a1 = *reinterpret_cast<const float4*>(&u.Xi[r0 + 1][c4 * 4]);
        float4 b0 = *reinterpret_cast<const float4*>(&Xj[tx     ][c4 * 4]);
        float4 b1 = *reinterpret_cast<const float4*>(&Xj[tx + 16][c4 * 4]);
        float4 b2 = *reinterpret_cast<const float4*>(&Xj[tx + 32][c4 * 4]);
        float4 b3 = *reinterpret_cast<const float4*>(&Xj[tx + 48][c4 * 4]);
        a0c0 = fmaf(a0.x,b0.x, fmaf(a0.y,b0.y, fmaf(a0.z,b0.z, fmaf(a0.w,b0.w, a0c0))));
        a0c1 = fmaf(a0.x,b1.x, fmaf(a0.y,b1.y, fmaf(a0.z,b1.z, fmaf(a0.w,b1.w, a0c1))));
        a0c2 = fmaf(a0.x,b2.x, fmaf(a0.y,b2.y, fmaf(a0.z,b2.z, fmaf(a0.w,b2.w, a0c2))));
        a0c3 = fmaf(a0.x,b3.x, fmaf(a0.y,b3.y, fmaf(a0.z,b3.z, fmaf(a0.w,b3.w, a0c3))));
        a1c0 = fmaf(a1.x,b0.x, fmaf(a1.y,b0.y, fmaf(a1.z,b0.z, fmaf(a1.w,b0.w, a1c0))));
        a1c1 = fmaf(a1.x,b1.x, fmaf(a1.y,b1.y, fmaf(a1.z,b1.z, fmaf(a1.w,b1.w, a1c1))));
        a1c2 = fmaf(a1.x,b2.x, fmaf(a1.y,b2.y, fmaf(a1.z,b2.z, fmaf(a1.w,b2.w, a1c2))));
        a1c3 = fmaf(a1.x,b3.x, fmaf(a1.y,b3.y, fmaf(a1.z,b3.z, fmaf(a1.w,b3.w, a1c3))));
    }

    {
        float* gp = kh ? g_p1 : g_p0;
        float accs[2][4] = {{a0c0,a0c1,a0c2,a0c3},{a1c0,a1c1,a1c2,a1c3}};
#pragma unroll
        for (int rr = 0; rr < 2; rr++) {
            const float ni = sni[r0 + rr];
            float* dst = gp + (i0 + r0 + rr) * N + j0;
#pragma unroll
            for (int c = 0; c < 4; c++) {
                const int col = tx + 16 * c;
                dst[col] = fmaf(-2.f, accs[rr][c], ni + snj[col]);
            }
        }
    }

    // ======================= Grid-wide sync =======================
    __syncthreads();
    __threadfence();
    if (tid == 0) {
        if (bid == 0) { g_sum = 0.0; g_cnt = 0ull; }   // pre-arrive: safe
        __threadfence();
        atomicAdd(&g_arrive, 1u);
        while (*((volatile unsigned*)&g_arrive) < NBLK) __nanosleep(64);
    }
    __syncthreads();

    // ======================= Phase 2: triplet hinge (2 anchors/block) =====
#pragma unroll
    for (int m = 0; m < 2; m++) u.p2.slbl[tid + 256 * m] = labels[tid + 256 * m];
    __syncthreads();

    for (int a = 2 * bid; a < 2 * bid + 2; a++) {
#pragma unroll
        for (int m = 0; m < 2; m++) {
            const int j = tid + 256 * m;
            const float sq = g_p0[a * N + j] + g_p1[a * N + j];
            u.p2.drow[j] = sqrtf(fmaxf(sq, 0.f));
        }
        if (tid == 0) u.p2.pcount = 0;
        __syncthreads();

        const int li = u.p2.slbl[a];
        float nk0 = (u.p2.slbl[tid]       != li) ? u.p2.drow[tid]       : CUDART_INF_F;
        float nk1 = (u.p2.slbl[tid + 256] != li) ? u.p2.drow[tid + 256] : CUDART_INF_F;
#pragma unroll
        for (int m = 0; m < 2; m++) {
            const int j = tid + 256 * m;
            if (u.p2.slbl[j] == li && j != a) {
                int p = atomicAdd(&u.p2.pcount, 1);
                u.p2.plist[p] = j;
            }
        }
        __syncthreads();

        const int np = u.p2.pcount;
        float sum = 0.f;
        unsigned cnt = 0;
        for (int p = 0; p < np; p++) {
            const float apm = u.p2.drow[u.p2.plist[p]] + MARGIN;
            const float v0 = apm - nk0;
            const float v1 = apm - nk1;
            if (v0 > 0.f) { sum += v0; cnt += (v0 > 1e-16f); }
            if (v1 > 0.f) { sum += v1; cnt += (v1 > 1e-16f); }
        }

#pragma unroll
        for (int off = 16; off; off >>= 1) {
            sum += __shfl_down_sync(0xffffffffu, sum, off);
            cnt += __shfl_down_sync(0xffffffffu, cnt, off);
        }
        if (lane == 0) { u.p2.red_s[w] = sum; u.p2.red_c[w] = cnt; }
        __syncthreads();
        if (tid == 0) {
            float s = 0.f; unsigned c = 0;
#pragma unroll
            for (int q = 0; q < 8; q++) { s += u.p2.red_s[q]; c += u.p2.red_c[q]; }
            atomicAdd(&g_sum, (double)s);
            atomicAdd(&g_cnt, (unsigned long long)c);
        }
        __syncthreads();
    }

    // ======================= Finalize: last block =======================
    __threadfence();
    if (tid == 0) {
        unsigned t = atomicAdd(&g_done, 1u);
        if (t == NBLK - 1) {
            double s = atomicAdd(&g_sum, 0.0);
            unsigned long long c = atomicAdd(&g_cnt, 0ull);
            out[0] = (float)(s / ((double)c + 1e-16));
            g_arrive = 0;            // reset for next graph replay
            g_done = 0;
            __threadfence();
        }
    }
}

extern "C" void kernel_launch(void* const* d_in, const int* in_sizes, int n_in,
                              void* d_out, int out_size) {
    const float* emb    = (const float*)d_in[0];   // [512, 128] fp32
    const int*   labels = (const int*)d_in[1];     // [512] int32
    float*       out    = (float*)d_out;

    fused_kernel<<<NBLK, NTHR>>>(emb, labels, out);
}